// round 12
// baseline (speedup 1.0000x reference)
#include <cuda_runtime.h>
#include <cstdint>

#define BB 16
#define NN 2000
#define EE 8000
#define DD 64
#define XROWS 10000
#define E2C 16000

// ---------------- scratch (device globals) ----------------
__device__ __align__(16) float g_h [BB * NN * DD];
__device__ __align__(16) float g_A [BB * NN * DD];
__device__ __align__(16) float g_C [BB * NN * DD];
__device__ __align__(16) float g_Bf[BB * EE * DD];
__device__ __align__(16) float g_M [DD * DD];     // W_edge@W2
__device__ __align__(16) float g_WA[DD * DD];     // W_node@W1
__device__ __align__(16) float g_WC[DD * DD];     // W_node@W3
__device__ __align__(16) float g_bA[DD];          // b_node@W1 + b_comb
__device__ __align__(16) float g_bC[DD];          // b_node@W3
__device__ float g_expl[BB * E2C];
__device__ float g_psum[BB * (E2C / 16)];
__device__ int   g_start[NN + 1];

__device__ __forceinline__ uint32_t f2tf(float f) {
    uint32_t r; asm("cvt.rna.tf32.f32 %0, %1;" : "=r"(r) : "f"(f)); return r;
}

// ---------------- prep: 3 mm64 + bias (4 blocks) ----------------
__device__ void mm64_dev(const float* __restrict__ A, const float* __restrict__ B,
                         float* __restrict__ O)
{
    __shared__ float sa[4096], sb[4096];
    int tid = threadIdx.x;
    for (int i = tid; i < 4096; i += 256) { sa[i] = A[i]; sb[i] = B[i]; }
    __syncthreads();
    for (int o = tid; o < 4096; o += 256) {
        int i = o >> 6, j = o & 63;
        float s = 0.f;
        #pragma unroll 16
        for (int k = 0; k < 64; k++) s += sa[i * 64 + k] * sb[k * 64 + j];
        O[o] = s;
    }
}

__global__ void prep_kernel(const float* __restrict__ W_edge,
                            const float* __restrict__ W_node,
                            const float* __restrict__ b_node,
                            const float* __restrict__ W_comb,
                            const float* __restrict__ b_comb)
{
    int blk = blockIdx.x, tid = threadIdx.x;
    if (blk == 0)      mm64_dev(W_edge, W_comb + 64 * 64,  g_M);
    else if (blk == 1) mm64_dev(W_node, W_comb,            g_WA);
    else if (blk == 2) mm64_dev(W_node, W_comb + 128 * 64, g_WC);
    else {
        if (tid < 128) {
            int c = tid & 63;
            const float* W = (tid < 64) ? W_comb : (W_comb + 128 * 64);
            float s = 0.f;
            #pragma unroll 16
            for (int k = 0; k < 64; k++) s += b_node[k] * W[k * 64 + c];
            if (tid < 64) g_bA[c] = s + b_comb[c];
            else          g_bC[c] = s;
        }
    }
}

// ---------------- ranges: per-src-node edge offsets (independent; idx 2) ----
__global__ void ranges_kernel(const int* __restrict__ src)
{
    int n = blockIdx.x * blockDim.x + threadIdx.x;
    if (n > NN) return;
    int lo = 0, hi = E2C;
    while (lo < hi) { int m = (lo + hi) >> 1; if (src[m] < n) lo = m + 1; else hi = m; }
    g_start[n] = lo;
}

// ---------------- tf32 mma.sync GEMM: 256x64 tile, K=64 ----------------
#define XS_S 68
#define SMEM_GEMM ((256 * XS_S + 64 * XS_S) * 4)   // 87040 bytes

__global__ void __launch_bounds__(256)
gemm_mma_kernel(const float* __restrict__ X,
                const float* __restrict__ W_node, const float* __restrict__ b_node)
{
    extern __shared__ uint32_t sm[];
    uint32_t* xs = sm;               // [256][68]
    uint32_t* ws = sm + 256 * XS_S;  // [64][68]

    int bid = blockIdx.x, set, rb;
    if (bid < 375) { set = bid / 125; rb = bid - set * 125; }
    else           { set = 3;         rb = bid - 375; }
    const float* Wp; const float* bp; float* Yp;
    if (set == 0)      { Wp = W_node; bp = b_node; Yp = g_h; }
    else if (set == 1) { Wp = g_WA;   bp = g_bA;   Yp = g_A; }
    else if (set == 2) { Wp = g_WC;   bp = g_bC;   Yp = g_C; }
    else               { Wp = g_M;    bp = nullptr; Yp = g_Bf; }
    const int bR  = (set < 3) ? NN : EE;
    const int off = (set < 3) ? EE : 0;
    const int rowBase = rb * 256;

    const int tid = threadIdx.x;

    #pragma unroll
    for (int i = 0; i < 16; i++) {
        int idx = tid + i * 256;
        int r   = idx >> 4;
        int c4  = idx & 15;
        int gr  = rowBase + r;
        int sb  = gr / bR;
        long srow = (long)sb * XROWS + off + (gr - sb * bR);
        float4 v = ((const float4*)X)[srow * 16 + c4];
        int base = r * XS_S + (c4 >> 1) * 8 + (c4 & 1);
        xs[base + 0] = f2tf(v.x);
        xs[base + 2] = f2tf(v.y);
        xs[base + 4] = f2tf(v.z);
        xs[base + 6] = f2tf(v.w);
    }
    #pragma unroll
    for (int i = 0; i < 4; i++) {
        int idx = tid + i * 256;
        int k   = idx >> 4;
        int c4  = idx & 15;
        float4 v = ((const float4*)Wp)[idx];
        int base = k * XS_S + (c4 & 1) * 32 + (c4 >> 1);
        ws[base + 0]  = f2tf(v.x);
        ws[base + 8]  = f2tf(v.y);
        ws[base + 16] = f2tf(v.z);
        ws[base + 24] = f2tf(v.w);
    }
    __syncthreads();

    const int warp = tid >> 5, lane = tid & 31;
    const int g = lane >> 2, t = lane & 3;
    const int r0 = warp * 16;

    float acc[2][8][4];
    #pragma unroll
    for (int m = 0; m < 2; m++)
        #pragma unroll
        for (int nt = 0; nt < 8; nt++)
            #pragma unroll
            for (int j = 0; j < 4; j++) acc[m][nt][j] = 0.f;

    #pragma unroll
    for (int ks = 0; ks < 8; ks++) {
        uint2 a00 = *(const uint2*)&xs[(r0 + g)       * XS_S + ks * 8 + 2 * t];
        uint2 a01 = *(const uint2*)&xs[(r0 + g + 8)   * XS_S + ks * 8 + 2 * t];
        uint2 a10 = *(const uint2*)&xs[(r0 + g + 128) * XS_S + ks * 8 + 2 * t];
        uint2 a11 = *(const uint2*)&xs[(r0 + g + 136) * XS_S + ks * 8 + 2 * t];
        const uint32_t* brow0 = ws + (ks * 8 + t)     * XS_S + g * 8;
        const uint32_t* brow1 = ws + (ks * 8 + t + 4) * XS_S + g * 8;
        uint4 B0a = *(const uint4*)brow0;
        uint4 B0b = *(const uint4*)(brow0 + 4);
        uint4 B1a = *(const uint4*)brow1;
        uint4 B1b = *(const uint4*)(brow1 + 4);
        uint32_t b0v[8] = {B0a.x, B0a.y, B0a.z, B0a.w, B0b.x, B0b.y, B0b.z, B0b.w};
        uint32_t b1v[8] = {B1a.x, B1a.y, B1a.z, B1a.w, B1b.x, B1b.y, B1b.z, B1b.w};
        #pragma unroll
        for (int nt = 0; nt < 8; nt++) {
            asm volatile(
                "mma.sync.aligned.m16n8k8.row.col.f32.tf32.tf32.f32 "
                "{%0,%1,%2,%3}, {%4,%5,%6,%7}, {%8,%9}, {%0,%1,%2,%3};"
                : "+f"(acc[0][nt][0]), "+f"(acc[0][nt][1]), "+f"(acc[0][nt][2]), "+f"(acc[0][nt][3])
                : "r"(a00.x), "r"(a01.x), "r"(a00.y), "r"(a01.y),
                  "r"(b0v[nt]), "r"(b1v[nt]));
            asm volatile(
                "mma.sync.aligned.m16n8k8.row.col.f32.tf32.tf32.f32 "
                "{%0,%1,%2,%3}, {%4,%5,%6,%7}, {%8,%9}, {%0,%1,%2,%3};"
                : "+f"(acc[1][nt][0]), "+f"(acc[1][nt][1]), "+f"(acc[1][nt][2]), "+f"(acc[1][nt][3])
                : "r"(a10.x), "r"(a11.x), "r"(a10.y), "r"(a11.y),
                  "r"(b0v[nt]), "r"(b1v[nt]));
        }
    }

    #pragma unroll
    for (int m = 0; m < 2; m++) {
        long row0 = rowBase + r0 + g + m * 128;
        long row1 = row0 + 8;
        #pragma unroll
        for (int nt = 0; nt < 8; nt++) {
            int c = nt * 8 + 2 * t;
            float bx = bp ? __ldg(bp + c)     : 0.f;
            float by = bp ? __ldg(bp + c + 1) : 0.f;
            ((float2*)(Yp + row0 * 64 + c))[0] =
                make_float2(acc[m][nt][0] + bx, acc[m][nt][1] + by);
            ((float2*)(Yp + row1 * 64 + c))[0] =
                make_float2(acc[m][nt][2] + bx, acc[m][nt][3] + by);
        }
    }
}

// ---------------- edge: 16 lanes per edge, float4; 16 edges per 256-thr block ----
__global__ void __launch_bounds__(256)
edge_kernel(const float* __restrict__ w_attn,
            const int* __restrict__ src,
            const int* __restrict__ dst,
            const int* __restrict__ eidx,
            float* __restrict__ out)
{
    __shared__ float wred[16];
    const int tid    = threadIdx.x;
    const int slot   = tid >> 4;
    const int lane16 = tid & 15;
    const int ge = blockIdx.x * 16 + slot;
    const int b  = ge / E2C;
    const int e  = ge - b * E2C;
    const int s = src[e], t = dst[e], q = eidx[e];

    float4 a = ((const float4*)(g_A  + ((long)b * NN + s) * DD))[lane16];
    float4 f = ((const float4*)(g_Bf + ((long)b * EE + q) * DD))[lane16];
    float4 c = ((const float4*)(g_C  + ((long)b * NN + t) * DD))[lane16];

    float4 v;
    v.x = a.x + f.x + c.x;
    v.y = a.y + f.y + c.y;
    v.z = a.z + f.z + c.z;
    v.w = a.w + f.w + c.w;
    v.x = v.x > 0.f ? v.x : 0.01f * v.x;
    v.y = v.y > 0.f ? v.y : 0.01f * v.y;
    v.z = v.z > 0.f ? v.z : 0.01f * v.z;
    v.w = v.w > 0.f ? v.w : 0.01f * v.w;

    ((float4*)(out + ((long)b * (E2C + NN) + e) * DD))[lane16] = v;

    float4 w = ((const float4*)w_attn)[lane16];
    float dot = v.x * w.x + v.y * w.y + v.z * w.z + v.w * w.w;
    #pragma unroll
    for (int o = 8; o; o >>= 1) dot += __shfl_xor_sync(0xffffffffu, dot, o);

    float ev = __expf(dot);
    if (lane16 == 0) { g_expl[ge] = ev; wred[slot] = ev; }
    __syncthreads();
    if (tid < 16) {
        float x = wred[tid];
        #pragma unroll
        for (int o = 8; o; o >>= 1) x += __shfl_xor_sync(0xffffu, x, o);
        if (tid == 0) g_psum[blockIdx.x] = x;
    }
}

// ---------------- aggregate: 400 blocks, 80 nodes/block (5 groups of 16) ----
// psum reduce amortized 5x; single wave (400 blocks).
__global__ void __launch_bounds__(256)
aggregate_kernel(const int* __restrict__ dst, float* __restrict__ out)
{
    __shared__ float red[256];
    __shared__ float s_inv;
    const int pb = E2C / 16;               // 1000 partials per batch
    const int tid = threadIdx.x;
    const int slot = tid >> 4, lane16 = tid & 15;
    const int b  = blockIdx.x / 25;        // 25 blocks per batch
    const int n0 = (blockIdx.x - b * 25) * 80;

    float s = 0.f;
    for (int j = tid; j < pb; j += 256) s += g_psum[b * pb + j];
    red[tid] = s; __syncthreads();
    #pragma unroll
    for (int st = 128; st > 0; st >>= 1) {
        if (tid < st) red[tid] += red[tid + st];
        __syncthreads();
    }
    if (tid == 0) s_inv = 1.0f / red[0];
    __syncthreads();

    const float inv = s_inv;
    const float4* hb = (const float4*)(g_h + (long)b * NN * DD);
    const float*  ex = g_expl + (long)b * E2C;
    float* outb = out + ((long)b * (E2C + NN) + E2C) * DD;

    #pragma unroll
    for (int g = 0; g < 5; g++) {
        const int n = n0 + g * 16 + slot;
        const int s0 = g_start[n], s1 = g_start[n + 1];
        float4 acc = make_float4(0.f, 0.f, 0.f, 0.f);
        for (int i = s0; i < s1; i++) {
            float al = ex[i];
            float4 hv = hb[(long)dst[i] * 16 + lane16];
            acc.x += al * hv.x;
            acc.y += al * hv.y;
            acc.z += al * hv.z;
            acc.w += al * hv.w;
        }
        acc.x *= inv; acc.y *= inv; acc.z *= inv; acc.w *= inv;
        ((float4*)(outb + (long)n * DD))[lane16] = acc;
    }
}

// ---------------- launch ----------------
extern "C" void kernel_launch(void* const* d_in, const int* in_sizes, int n_in,
                              void* d_out, int out_size)
{
    const float* x      = (const float*)d_in[0];
    const float* W_edge = (const float*)d_in[1];
    const float* W_node = (const float*)d_in[2];
    const float* b_node = (const float*)d_in[3];
    const float* W_comb = (const float*)d_in[4];
    const float* b_comb = (const float*)d_in[5];
    const float* w_attn = (const float*)d_in[6];
    const int*   src    = (const int*)d_in[7];
    const int*   dst    = (const int*)d_in[8];
    const int*   eidx   = (const int*)d_in[9];
    float* out = (float*)d_out;

    cudaFuncSetAttribute(gemm_mma_kernel, cudaFuncAttributeMaxDynamicSharedMemorySize, SMEM_GEMM);

    prep_kernel     <<<4, 256>>>(W_edge, W_node, b_node, W_comb, b_comb);       // idx 0
    gemm_mma_kernel <<<875, 256, SMEM_GEMM>>>(x, W_node, b_node);               // idx 1
    ranges_kernel   <<<8, 256>>>(src);                                          // idx 2
    edge_kernel     <<<BB * E2C / 16, 256>>>(w_attn, src, dst, eidx, out);      // idx 3 (profiled)
    aggregate_kernel<<<BB * 25, 256>>>(dst, out);                               // idx 4
}

// round 13
// speedup vs baseline: 1.3823x; 1.3823x over previous
#include <cuda_runtime.h>
#include <cstdint>

#define BB 16
#define NN 2000
#define EE 8000
#define DD 64
#define XROWS 10000
#define E2C 16000

// ---------------- scratch (device globals) ----------------
__device__ __align__(16) float g_h [BB * NN * DD];
__device__ __align__(16) float g_A [BB * NN * DD];
__device__ __align__(16) float g_C [BB * NN * DD];
__device__ __align__(16) float g_Bf[BB * EE * DD];
__device__ __align__(16) float g_M [DD * DD];     // W_edge@W2
__device__ __align__(16) float g_WA[DD * DD];     // W_node@W1
__device__ __align__(16) float g_WC[DD * DD];     // W_node@W3
__device__ __align__(16) float g_bA[DD];          // b_node@W1 + b_comb
__device__ __align__(16) float g_bC[DD];          // b_node@W3
__device__ float g_expl[BB * E2C];
__device__ float g_psum[BB * (E2C / 16)];
__device__ int   g_start[NN + 1];

__device__ __forceinline__ uint32_t f2tf(float f) {
    uint32_t r; asm("cvt.rna.tf32.f32 %0, %1;" : "=r"(r) : "f"(f)); return r;
}

// ---------------- prep: 3 mm64 + bias + ranges, one kernel ----------------
__device__ void mm64_dev(const float* __restrict__ A, const float* __restrict__ B,
                         float* __restrict__ O)
{
    __shared__ float sa[4096], sb[4096];
    int tid = threadIdx.x;
    for (int i = tid; i < 4096; i += 256) { sa[i] = A[i]; sb[i] = B[i]; }
    __syncthreads();
    for (int o = tid; o < 4096; o += 256) {
        int i = o >> 6, j = o & 63;
        float s = 0.f;
        #pragma unroll 16
        for (int k = 0; k < 64; k++) s += sa[i * 64 + k] * sb[k * 64 + j];
        O[o] = s;
    }
}

__global__ void prep_kernel(const float* __restrict__ W_edge,
                            const float* __restrict__ W_node,
                            const float* __restrict__ b_node,
                            const float* __restrict__ W_comb,
                            const float* __restrict__ b_comb,
                            const int* __restrict__ src)
{
    int blk = blockIdx.x, tid = threadIdx.x;
    if (blk == 0)      mm64_dev(W_edge, W_comb + 64 * 64,  g_M);
    else if (blk == 1) mm64_dev(W_node, W_comb,            g_WA);
    else if (blk == 2) mm64_dev(W_node, W_comb + 128 * 64, g_WC);
    else if (blk == 3) {
        if (tid < 128) {
            int c = tid & 63;
            const float* W = (tid < 64) ? W_comb : (W_comb + 128 * 64);
            float s = 0.f;
            #pragma unroll 16
            for (int k = 0; k < 64; k++) s += b_node[k] * W[k * 64 + c];
            if (tid < 64) g_bA[c] = s + b_comb[c];
            else          g_bC[c] = s;
        }
    } else {
        for (int n = tid; n <= NN; n += 256) {
            int lo = 0, hi = E2C;
            while (lo < hi) { int m = (lo + hi) >> 1; if (src[m] < n) lo = m + 1; else hi = m; }
            g_start[n] = lo;
        }
    }
}

// ---------------- tf32 mma.sync GEMM: 256x64 tile, K=64 ----------------
#define XS_S 68
#define SMEM_GEMM ((256 * XS_S + 64 * XS_S) * 4)   // 87040 bytes

__global__ void __launch_bounds__(256)
gemm_mma_kernel(const float* __restrict__ X,
                const float* __restrict__ W_node, const float* __restrict__ b_node)
{
    extern __shared__ uint32_t sm[];
    uint32_t* xs = sm;               // [256][68]
    uint32_t* ws = sm + 256 * XS_S;  // [64][68]

    int bid = blockIdx.x, set, rb;
    if (bid < 375) { set = bid / 125; rb = bid - set * 125; }
    else           { set = 3;         rb = bid - 375; }
    const float* Wp; const float* bp; float* Yp;
    if (set == 0)      { Wp = W_node; bp = b_node; Yp = g_h; }
    else if (set == 1) { Wp = g_WA;   bp = g_bA;   Yp = g_A; }
    else if (set == 2) { Wp = g_WC;   bp = g_bC;   Yp = g_C; }
    else               { Wp = g_M;    bp = nullptr; Yp = g_Bf; }
    const int bR  = (set < 3) ? NN : EE;
    const int off = (set < 3) ? EE : 0;
    const int rowBase = rb * 256;

    const int tid = threadIdx.x;

    #pragma unroll
    for (int i = 0; i < 16; i++) {
        int idx = tid + i * 256;
        int r   = idx >> 4;
        int c4  = idx & 15;
        int gr  = rowBase + r;
        int sb  = gr / bR;
        long srow = (long)sb * XROWS + off + (gr - sb * bR);
        float4 v = ((const float4*)X)[srow * 16 + c4];
        int base = r * XS_S + (c4 >> 1) * 8 + (c4 & 1);
        xs[base + 0] = f2tf(v.x);
        xs[base + 2] = f2tf(v.y);
        xs[base + 4] = f2tf(v.z);
        xs[base + 6] = f2tf(v.w);
    }
    #pragma unroll
    for (int i = 0; i < 4; i++) {
        int idx = tid + i * 256;
        int k   = idx >> 4;
        int c4  = idx & 15;
        float4 v = ((const float4*)Wp)[idx];
        int base = k * XS_S + (c4 & 1) * 32 + (c4 >> 1);
        ws[base + 0]  = f2tf(v.x);
        ws[base + 8]  = f2tf(v.y);
        ws[base + 16] = f2tf(v.z);
        ws[base + 24] = f2tf(v.w);
    }
    __syncthreads();

    const int warp = tid >> 5, lane = tid & 31;
    const int g = lane >> 2, t = lane & 3;
    const int r0 = warp * 16;

    float acc[2][8][4];
    #pragma unroll
    for (int m = 0; m < 2; m++)
        #pragma unroll
        for (int nt = 0; nt < 8; nt++)
            #pragma unroll
            for (int j = 0; j < 4; j++) acc[m][nt][j] = 0.f;

    #pragma unroll
    for (int ks = 0; ks < 8; ks++) {
        uint2 a00 = *(const uint2*)&xs[(r0 + g)       * XS_S + ks * 8 + 2 * t];
        uint2 a01 = *(const uint2*)&xs[(r0 + g + 8)   * XS_S + ks * 8 + 2 * t];
        uint2 a10 = *(const uint2*)&xs[(r0 + g + 128) * XS_S + ks * 8 + 2 * t];
        uint2 a11 = *(const uint2*)&xs[(r0 + g + 136) * XS_S + ks * 8 + 2 * t];
        const uint32_t* brow0 = ws + (ks * 8 + t)     * XS_S + g * 8;
        const uint32_t* brow1 = ws + (ks * 8 + t + 4) * XS_S + g * 8;
        uint4 B0a = *(const uint4*)brow0;
        uint4 B0b = *(const uint4*)(brow0 + 4);
        uint4 B1a = *(const uint4*)brow1;
        uint4 B1b = *(const uint4*)(brow1 + 4);
        uint32_t b0v[8] = {B0a.x, B0a.y, B0a.z, B0a.w, B0b.x, B0b.y, B0b.z, B0b.w};
        uint32_t b1v[8] = {B1a.x, B1a.y, B1a.z, B1a.w, B1b.x, B1b.y, B1b.z, B1b.w};
        #pragma unroll
        for (int nt = 0; nt < 8; nt++) {
            asm volatile(
                "mma.sync.aligned.m16n8k8.row.col.f32.tf32.tf32.f32 "
                "{%0,%1,%2,%3}, {%4,%5,%6,%7}, {%8,%9}, {%0,%1,%2,%3};"
                : "+f"(acc[0][nt][0]), "+f"(acc[0][nt][1]), "+f"(acc[0][nt][2]), "+f"(acc[0][nt][3])
                : "r"(a00.x), "r"(a01.x), "r"(a00.y), "r"(a01.y),
                  "r"(b0v[nt]), "r"(b1v[nt]));
            asm volatile(
                "mma.sync.aligned.m16n8k8.row.col.f32.tf32.tf32.f32 "
                "{%0,%1,%2,%3}, {%4,%5,%6,%7}, {%8,%9}, {%0,%1,%2,%3};"
                : "+f"(acc[1][nt][0]), "+f"(acc[1][nt][1]), "+f"(acc[1][nt][2]), "+f"(acc[1][nt][3])
                : "r"(a10.x), "r"(a11.x), "r"(a10.y), "r"(a11.y),
                  "r"(b0v[nt]), "r"(b1v[nt]));
        }
    }

    #pragma unroll
    for (int m = 0; m < 2; m++) {
        long row0 = rowBase + r0 + g + m * 128;
        long row1 = row0 + 8;
        #pragma unroll
        for (int nt = 0; nt < 8; nt++) {
            int c = nt * 8 + 2 * t;
            float bx = bp ? __ldg(bp + c)     : 0.f;
            float by = bp ? __ldg(bp + c + 1) : 0.f;
            ((float2*)(Yp + row0 * 64 + c))[0] =
                make_float2(acc[m][nt][0] + bx, acc[m][nt][1] + by);
            ((float2*)(Yp + row1 * 64 + c))[0] =
                make_float2(acc[m][nt][2] + bx, acc[m][nt][3] + by);
        }
    }
}

// ---------------- edge: 16 lanes per edge, float4; 16 edges per 256-thr block ----
__global__ void __launch_bounds__(256)
edge_kernel(const float* __restrict__ w_attn,
            const int* __restrict__ src,
            const int* __restrict__ dst,
            const int* __restrict__ eidx,
            float* __restrict__ out)
{
    __shared__ float wred[16];
    const int tid    = threadIdx.x;
    const int slot   = tid >> 4;
    const int lane16 = tid & 15;
    const int ge = blockIdx.x * 16 + slot;
    const int b  = ge / E2C;
    const int e  = ge - b * E2C;
    const int s = src[e], t = dst[e], q = eidx[e];

    float4 a = ((const float4*)(g_A  + ((long)b * NN + s) * DD))[lane16];
    float4 f = ((const float4*)(g_Bf + ((long)b * EE + q) * DD))[lane16];
    float4 c = ((const float4*)(g_C  + ((long)b * NN + t) * DD))[lane16];

    float4 v;
    v.x = a.x + f.x + c.x;
    v.y = a.y + f.y + c.y;
    v.z = a.z + f.z + c.z;
    v.w = a.w + f.w + c.w;
    v.x = v.x > 0.f ? v.x : 0.01f * v.x;
    v.y = v.y > 0.f ? v.y : 0.01f * v.y;
    v.z = v.z > 0.f ? v.z : 0.01f * v.z;
    v.w = v.w > 0.f ? v.w : 0.01f * v.w;

    ((float4*)(out + ((long)b * (E2C + NN) + e) * DD))[lane16] = v;

    float4 w = ((const float4*)w_attn)[lane16];
    float dot = v.x * w.x + v.y * w.y + v.z * w.z + v.w * w.w;
    #pragma unroll
    for (int o = 8; o; o >>= 1) dot += __shfl_xor_sync(0xffffffffu, dot, o);

    float ev = __expf(dot);
    if (lane16 == 0) { g_expl[ge] = ev; wred[slot] = ev; }
    __syncthreads();
    if (tid < 16) {
        float x = wred[tid];
        #pragma unroll
        for (int o = 8; o; o >>= 1) x += __shfl_xor_sync(0xffffu, x, o);
        if (tid == 0) g_psum[blockIdx.x] = x;
    }
}

// ---------------- aggregate (sum fused): 16 lanes per node, float4, serial loop ----
// identical to r11 except: psum reduction via warp shuffles (2 syncs, not 9).
__global__ void __launch_bounds__(256)
aggregate_kernel(const int* __restrict__ dst, float* __restrict__ out)
{
    __shared__ float wpart[8];
    __shared__ float s_inv;
    const int pb = E2C / 16;               // 1000 edge-blocks per batch
    const int tid = threadIdx.x;
    const int warp = tid >> 5, lane = tid & 31;
    const int slot = tid >> 4, lane16 = tid & 15;
    const int b = blockIdx.x / 125;

    float s = 0.f;
    for (int j = tid; j < pb; j += 256) s += g_psum[b * pb + j];
    #pragma unroll
    for (int o = 16; o; o >>= 1) s += __shfl_xor_sync(0xffffffffu, s, o);
    if (lane == 0) wpart[warp] = s;
    __syncthreads();
    if (tid < 8) {
        float x = wpart[tid];
        #pragma unroll
        for (int o = 4; o; o >>= 1) x += __shfl_xor_sync(0xffu, x, o);
        if (tid == 0) s_inv = 1.0f / x;
    }
    __syncthreads();

    const int n = (blockIdx.x - b * 125) * 16 + slot;
    const int s0 = g_start[n], s1 = g_start[n + 1];
    const float inv = s_inv;
    const float4* hb = (const float4*)(g_h + (long)b * NN * DD);
    const float*  ex = g_expl + (long)b * E2C;
    float4 acc = make_float4(0.f, 0.f, 0.f, 0.f);
    for (int i = s0; i < s1; i++) {
        float al = ex[i];
        float4 hv = hb[(long)dst[i] * 16 + lane16];
        acc.x += al * hv.x;
        acc.y += al * hv.y;
        acc.z += al * hv.z;
        acc.w += al * hv.w;
    }
    acc.x *= inv; acc.y *= inv; acc.z *= inv; acc.w *= inv;
    ((float4*)(out + ((long)b * (E2C + NN) + E2C + n) * DD))[lane16] = acc;
}

// ---------------- launch ----------------
extern "C" void kernel_launch(void* const* d_in, const int* in_sizes, int n_in,
                              void* d_out, int out_size)
{
    const float* x      = (const float*)d_in[0];
    const float* W_edge = (const float*)d_in[1];
    const float* W_node = (const float*)d_in[2];
    const float* b_node = (const float*)d_in[3];
    const float* W_comb = (const float*)d_in[4];
    const float* b_comb = (const float*)d_in[5];
    const float* w_attn = (const float*)d_in[6];
    const int*   src    = (const int*)d_in[7];
    const int*   dst    = (const int*)d_in[8];
    const int*   eidx   = (const int*)d_in[9];
    float* out = (float*)d_out;

    cudaFuncSetAttribute(gemm_mma_kernel, cudaFuncAttributeMaxDynamicSharedMemorySize, SMEM_GEMM);

    prep_kernel     <<<5, 256>>>(W_edge, W_node, b_node, W_comb, b_comb, src);  // idx 0
    gemm_mma_kernel <<<875, 256, SMEM_GEMM>>>(x, W_node, b_node);               // idx 1
    edge_kernel     <<<BB * E2C / 16, 256>>>(w_attn, src, dst, eidx, out);      // idx 2
    aggregate_kernel<<<BB * 125, 256>>>(dst, out);                              // idx 3 (profiled)
}

// round 15
// speedup vs baseline: 1.4263x; 1.0319x over previous
#include <cuda_runtime.h>
#include <cuda_fp16.h>
#include <cstdint>

#define BB 16
#define NN 2000
#define EE 8000
#define DD 64
#define XROWS 10000
#define E2C 16000

// ---------------- scratch (device globals) ----------------
__device__ __align__(16) float  g_h [BB * NN * DD];          // fp32 (feeds h_out)
__device__ __align__(16) __half g_Ah [BB * NN * DD];         // fp16 A = h@W1 + bA
__device__ __align__(16) __half g_Ch [BB * NN * DD];         // fp16 C = h@W3 + bC
__device__ __align__(16) __half g_Bfh[BB * EE * DD];         // fp16 Bf = edges@M
__device__ __align__(16) float g_M [DD * DD];
__device__ __align__(16) float g_WA[DD * DD];
__device__ __align__(16) float g_WC[DD * DD];
__device__ __align__(16) float g_bA[DD];                     // b_node@W1 + b_comb
__device__ __align__(16) float g_bC[DD];                     // b_node@W3
__device__ float g_expl[BB * E2C];
__device__ float g_psum[BB * (E2C / 16)];
__device__ int   g_start[NN + 1];

__device__ __forceinline__ uint32_t f2tf(float f) {
    uint32_t r; asm("cvt.rna.tf32.f32 %0, %1;" : "=r"(r) : "f"(f)); return r;
}

// ---------------- prep: 3 mm64 + bias + ranges, one kernel ----------------
__device__ void mm64_dev(const float* __restrict__ A, const float* __restrict__ B,
                         float* __restrict__ O)
{
    __shared__ float sa[4096], sb[4096];
    int tid = threadIdx.x;
    for (int i = tid; i < 4096; i += 256) { sa[i] = A[i]; sb[i] = B[i]; }
    __syncthreads();
    for (int o = tid; o < 4096; o += 256) {
        int i = o >> 6, j = o & 63;
        float s = 0.f;
        #pragma unroll 16
        for (int k = 0; k < 64; k++) s += sa[i * 64 + k] * sb[k * 64 + j];
        O[o] = s;
    }
}

__global__ void prep_kernel(const float* __restrict__ W_edge,
                            const float* __restrict__ W_node,
                            const float* __restrict__ b_node,
                            const float* __restrict__ W_comb,
                            const float* __restrict__ b_comb,
                            const int* __restrict__ src)
{
    int blk = blockIdx.x, tid = threadIdx.x;
    if (blk == 0)      mm64_dev(W_edge, W_comb + 64 * 64,  g_M);
    else if (blk == 1) mm64_dev(W_node, W_comb,            g_WA);
    else if (blk == 2) mm64_dev(W_node, W_comb + 128 * 64, g_WC);
    else if (blk == 3) {
        if (tid < 128) {
            int c = tid & 63;
            const float* W = (tid < 64) ? W_comb : (W_comb + 128 * 64);
            float s = 0.f;
            #pragma unroll 16
            for (int k = 0; k < 64; k++) s += b_node[k] * W[k * 64 + c];
            if (tid < 64) g_bA[c] = s + b_comb[c];
            else          g_bC[c] = s;
        }
    } else {
        for (int n = tid; n <= NN; n += 256) {
            int lo = 0, hi = E2C;
            while (lo < hi) { int m = (lo + hi) >> 1; if (src[m] < n) lo = m + 1; else hi = m; }
            g_start[n] = lo;
        }
    }
}

// ---------------- tf32 mma.sync GEMM: 256x64 tile, K=64 ----------------
// set 0 (h) -> fp32; sets 1,2,3 (A, C, Bf) -> fp16.
#define XS_S 68
#define SMEM_GEMM ((256 * XS_S + 64 * XS_S) * 4)   // 87040 bytes

__global__ void __launch_bounds__(256)
gemm_mma_kernel(const float* __restrict__ X,
                const float* __restrict__ W_node, const float* __restrict__ b_node)
{
    extern __shared__ uint32_t sm[];
    uint32_t* xs = sm;               // [256][68]
    uint32_t* ws = sm + 256 * XS_S;  // [64][68]

    int bid = blockIdx.x, set, rb;
    if (bid < 375) { set = bid / 125; rb = bid - set * 125; }
    else           { set = 3;         rb = bid - 375; }
    const float* Wp; const float* bp;
    float*  Yf = nullptr;
    __half* Yh = nullptr;
    if (set == 0)      { Wp = W_node; bp = b_node; Yf = g_h; }
    else if (set == 1) { Wp = g_WA;   bp = g_bA;   Yh = g_Ah; }
    else if (set == 2) { Wp = g_WC;   bp = g_bC;   Yh = g_Ch; }
    else               { Wp = g_M;    bp = nullptr; Yh = g_Bfh; }
    const int bR  = (set < 3) ? NN : EE;
    const int off = (set < 3) ? EE : 0;
    const int rowBase = rb * 256;

    const int tid = threadIdx.x;

    #pragma unroll
    for (int i = 0; i < 16; i++) {
        int idx = tid + i * 256;
        int r   = idx >> 4;
        int c4  = idx & 15;
        int gr  = rowBase + r;
        int sb  = gr / bR;
        long srow = (long)sb * XROWS + off + (gr - sb * bR);
        float4 v = ((const float4*)X)[srow * 16 + c4];
        int base = r * XS_S + (c4 >> 1) * 8 + (c4 & 1);
        xs[base + 0] = f2tf(v.x);
        xs[base + 2] = f2tf(v.y);
        xs[base + 4] = f2tf(v.z);
        xs[base + 6] = f2tf(v.w);
    }
    #pragma unroll
    for (int i = 0; i < 4; i++) {
        int idx = tid + i * 256;
        int k   = idx >> 4;
        int c4  = idx & 15;
        float4 v = ((const float4*)Wp)[idx];
        int base = k * XS_S + (c4 & 1) * 32 + (c4 >> 1);
        ws[base + 0]  = f2tf(v.x);
        ws[base + 8]  = f2tf(v.y);
        ws[base + 16] = f2tf(v.z);
        ws[base + 24] = f2tf(v.w);
    }
    __syncthreads();

    const int warp = tid >> 5, lane = tid & 31;
    const int g = lane >> 2, t = lane & 3;
    const int r0 = warp * 16;

    float acc[2][8][4];
    #pragma unroll
    for (int m = 0; m < 2; m++)
        #pragma unroll
        for (int nt = 0; nt < 8; nt++)
            #pragma unroll
            for (int j = 0; j < 4; j++) acc[m][nt][j] = 0.f;

    #pragma unroll
    for (int ks = 0; ks < 8; ks++) {
        uint2 a00 = *(const uint2*)&xs[(r0 + g)       * XS_S + ks * 8 + 2 * t];
        uint2 a01 = *(const uint2*)&xs[(r0 + g + 8)   * XS_S + ks * 8 + 2 * t];
        uint2 a10 = *(const uint2*)&xs[(r0 + g + 128) * XS_S + ks * 8 + 2 * t];
        uint2 a11 = *(const uint2*)&xs[(r0 + g + 136) * XS_S + ks * 8 + 2 * t];
        const uint32_t* brow0 = ws + (ks * 8 + t)     * XS_S + g * 8;
        const uint32_t* brow1 = ws + (ks * 8 + t + 4) * XS_S + g * 8;
        uint4 B0a = *(const uint4*)brow0;
        uint4 B0b = *(const uint4*)(brow0 + 4);
        uint4 B1a = *(const uint4*)brow1;
        uint4 B1b = *(const uint4*)(brow1 + 4);
        uint32_t b0v[8] = {B0a.x, B0a.y, B0a.z, B0a.w, B0b.x, B0b.y, B0b.z, B0b.w};
        uint32_t b1v[8] = {B1a.x, B1a.y, B1a.z, B1a.w, B1b.x, B1b.y, B1b.z, B1b.w};
        #pragma unroll
        for (int nt = 0; nt < 8; nt++) {
            asm volatile(
                "mma.sync.aligned.m16n8k8.row.col.f32.tf32.tf32.f32 "
                "{%0,%1,%2,%3}, {%4,%5,%6,%7}, {%8,%9}, {%0,%1,%2,%3};"
                : "+f"(acc[0][nt][0]), "+f"(acc[0][nt][1]), "+f"(acc[0][nt][2]), "+f"(acc[0][nt][3])
                : "r"(a00.x), "r"(a01.x), "r"(a00.y), "r"(a01.y),
                  "r"(b0v[nt]), "r"(b1v[nt]));
            asm volatile(
                "mma.sync.aligned.m16n8k8.row.col.f32.tf32.tf32.f32 "
                "{%0,%1,%2,%3}, {%4,%5,%6,%7}, {%8,%9}, {%0,%1,%2,%3};"
                : "+f"(acc[1][nt][0]), "+f"(acc[1][nt][1]), "+f"(acc[1][nt][2]), "+f"(acc[1][nt][3])
                : "r"(a10.x), "r"(a11.x), "r"(a10.y), "r"(a11.y),
                  "r"(b0v[nt]), "r"(b1v[nt]));
        }
    }

    #pragma unroll
    for (int m = 0; m < 2; m++) {
        long row0 = rowBase + r0 + g + m * 128;
        long row1 = row0 + 8;
        #pragma unroll
        for (int nt = 0; nt < 8; nt++) {
            int c = nt * 8 + 2 * t;
            float bx = bp ? __ldg(bp + c)     : 0.f;
            float by = bp ? __ldg(bp + c + 1) : 0.f;
            float v00 = acc[m][nt][0] + bx, v01 = acc[m][nt][1] + by;
            float v10 = acc[m][nt][2] + bx, v11 = acc[m][nt][3] + by;
            if (set == 0) {
                ((float2*)(Yf + row0 * 64 + c))[0] = make_float2(v00, v01);
                ((float2*)(Yf + row1 * 64 + c))[0] = make_float2(v10, v11);
            } else {
                ((__half2*)Yh)[row0 * 32 + (c >> 1)] = __floats2half2_rn(v00, v01);
                ((__half2*)Yh)[row1 * 32 + (c >> 1)] = __floats2half2_rn(v10, v11);
            }
        }
    }
}

// ---------------- edge: 16 lanes per edge; fp16 gathers, fp32 math ----------------
__global__ void __launch_bounds__(256)
edge_kernel(const float* __restrict__ w_attn,
            const int* __restrict__ src,
            const int* __restrict__ dst,
            const int* __restrict__ eidx,
            float* __restrict__ out)
{
    __shared__ float wred[16];
    const int tid    = threadIdx.x;
    const int slot   = tid >> 4;
    const int lane16 = tid & 15;
    const int ge = blockIdx.x * 16 + slot;
    const int b  = ge / E2C;
    const int e  = ge - b * E2C;
    const int s = src[e], t = dst[e], q = eidx[e];

    // each lane: 4 dims = 2x __half2 = one 8-byte load per operand
    uint2 ua = ((const uint2*)(g_Ah  + ((long)b * NN + s) * DD))[lane16];
    uint2 uf = ((const uint2*)(g_Bfh + ((long)b * EE + q) * DD))[lane16];
    uint2 uc = ((const uint2*)(g_Ch  + ((long)b * NN + t) * DD))[lane16];

    float2 a01 = __half22float2(*(const __half2*)&ua.x);
    float2 a23 = __half22float2(*(const __half2*)&ua.y);
    float2 f01 = __half22float2(*(const __half2*)&uf.x);
    float2 f23 = __half22float2(*(const __half2*)&uf.y);
    float2 c01 = __half22float2(*(const __half2*)&uc.x);
    float2 c23 = __half22float2(*(const __half2*)&uc.y);

    float4 v;
    v.x = a01.x + f01.x + c01.x;
    v.y = a01.y + f01.y + c01.y;
    v.z = a23.x + f23.x + c23.x;
    v.w = a23.y + f23.y + c23.y;
    v.x = v.x > 0.f ? v.x : 0.01f * v.x;
    v.y = v.y > 0.f ? v.y : 0.01f * v.y;
    v.z = v.z > 0.f ? v.z : 0.01f * v.z;
    v.w = v.w > 0.f ? v.w : 0.01f * v.w;

    ((float4*)(out + ((long)b * (E2C + NN) + e) * DD))[lane16] = v;

    float4 w = ((const float4*)w_attn)[lane16];
    float dot = v.x * w.x + v.y * w.y + v.z * w.z + v.w * w.w;
    #pragma unroll
    for (int o = 8; o; o >>= 1) dot += __shfl_xor_sync(0xffffffffu, dot, o);

    float ev = __expf(dot);
    if (lane16 == 0) { g_expl[ge] = ev; wred[slot] = ev; }
    __syncthreads();
    if (tid < 16) {
        float x = wred[tid];
        #pragma unroll
        for (int o = 8; o; o >>= 1) x += __shfl_xor_sync(0xffffu, x, o);
        if (tid == 0) g_psum[blockIdx.x] = x;
    }
}

// ---------------- aggregate (sum fused): 16 lanes per node, float4, serial loop ----
__global__ void __launch_bounds__(256)
aggregate_kernel(const int* __restrict__ dst, float* __restrict__ out)
{
    __shared__ float wpart[8];
    __shared__ float s_inv;
    const int pb = E2C / 16;
    const int tid = threadIdx.x;
    const int warp = tid >> 5, lane = tid & 31;
    const int slot = tid >> 4, lane16 = tid & 15;
    const int b = blockIdx.x / 125;

    float s = 0.f;
    for (int j = tid; j < pb; j += 256) s += g_psum[b * pb + j];
    #pragma unroll
    for (int o = 16; o; o >>= 1) s += __shfl_xor_sync(0xffffffffu, s, o);
    if (lane == 0) wpart[warp] = s;
    __syncthreads();
    if (tid < 8) {
        float x = wpart[tid];
        #pragma unroll
        for (int o = 4; o; o >>= 1) x += __shfl_xor_sync(0xffu, x, o);
        if (tid == 0) s_inv = 1.0f / x;
    }
    __syncthreads();

    const int n = (blockIdx.x - b * 125) * 16 + slot;
    const int s0 = g_start[n], s1 = g_start[n + 1];
    const float inv = s_inv;
    const float4* hb = (const float4*)(g_h + (long)b * NN * DD);
    const float*  ex = g_expl + (long)b * E2C;
    float4 acc = make_float4(0.f, 0.f, 0.f, 0.f);
    for (int i = s0; i < s1; i++) {
        float al = ex[i];
        float4 hv = hb[(long)dst[i] * 16 + lane16];
        acc.x += al * hv.x;
        acc.y += al * hv.y;
        acc.z += al * hv.z;
        acc.w += al * hv.w;
    }
    acc.x *= inv; acc.y *= inv; acc.z *= inv; acc.w *= inv;
    ((float4*)(out + ((long)b * (E2C + NN) + E2C + n) * DD))[lane16] = acc;
}

// ---------------- launch ----------------
extern "C" void kernel_launch(void* const* d_in, const int* in_sizes, int n_in,
                              void* d_out, int out_size)
{
    const float* x      = (const float*)d_in[0];
    const float* W_edge = (const float*)d_in[1];
    const float* W_node = (const float*)d_in[2];
    const float* b_node = (const float*)d_in[3];
    const float* W_comb = (const float*)d_in[4];
    const float* b_comb = (const float*)d_in[5];
    const float* w_attn = (const float*)d_in[6];
    const int*   src    = (const int*)d_in[7];
    const int*   dst    = (const int*)d_in[8];
    const int*   eidx   = (const int*)d_in[9];
    float* out = (float*)d_out;

    cudaFuncSetAttribute(gemm_mma_kernel, cudaFuncAttributeMaxDynamicSharedMemorySize, SMEM_GEMM);

    prep_kernel     <<<5, 256>>>(W_edge, W_node, b_node, W_comb, b_comb, src);  // idx 0
    gemm_mma_kernel <<<875, 256, SMEM_GEMM>>>(x, W_node, b_node);               // idx 1
    edge_kernel     <<<BB * E2C / 16, 256>>>(w_attn, src, dst, eidx, out);      // idx 2
    aggregate_kernel<<<BB * 125, 256>>>(dst, out);                              // idx 3 (profiled)
}